// round 14
// baseline (speedup 1.0000x reference)
#include <cuda_runtime.h>

#define E_EDGES 2000000
#define N_NODES 50000
#define D 32
#define NTILES (E_EDGES / 16)

// ---------------- scratch ----------------
__device__ unsigned g_sh[N_NODES * 32];   // fp16 table (PERMUTED): 0-15 s0, 16-31 s1
__device__ float    g_dsum[N_NODES];      // softmax denominators (-> reciprocals)

__device__ __forceinline__ float lrelu(float x) { return fmaxf(x, 0.01f * x); }
__device__ __forceinline__ void red_add1(float* p, float v) {
    asm volatile("red.global.add.f32 [%0], %1;" :: "l"(p), "f"(v) : "memory");
}
__device__ __forceinline__ unsigned packh2(float lo, float hi) {
    unsigned r; asm("cvt.rn.f16x2.f32 %0, %1, %2;" : "=r"(r) : "f"(hi), "f"(lo)); return r;
}
__device__ __forceinline__ void red_h2v2(unsigned* p, unsigned a, unsigned b) {
    asm volatile("red.global.add.noftz.v2.f16x2 [%0], {%1,%2};"
                 :: "l"(p), "r"(a), "r"(b) : "memory");
}

__device__ __forceinline__ void mma16(float& c0, float& c1, float& c2, float& c3,
                                      unsigned a0, unsigned a1, unsigned a2, unsigned a3,
                                      unsigned b0, unsigned b1) {
    asm("mma.sync.aligned.m16n8k16.row.col.f32.f16.f16.f32 "
        "{%0,%1,%2,%3},{%4,%5,%6,%7},{%8,%9},{%0,%1,%2,%3};"
        : "+f"(c0), "+f"(c1), "+f"(c2), "+f"(c3)
        : "r"(a0), "r"(a1), "r"(a2), "r"(a3), "r"(b0), "r"(b1));
}

__device__ __forceinline__ void mm_tile_r(const unsigned A[2][4], const uint2 W[8],
                                          float C[4][4]) {
#pragma unroll
    for (int kb = 0; kb < 2; kb++)
#pragma unroll
        for (int nb = 0; nb < 4; nb++) {
            uint2 b = W[kb * 4 + nb];
            mma16(C[nb][0], C[nb][1], C[nb][2], C[nb][3],
                  A[kb][0], A[kb][1], A[kb][2], A[kb][3], b.x, b.y);
        }
}
__device__ __forceinline__ void mm_tile_s(const unsigned A[2][4], const uint2* sB,
                                          float C[4][4], int lane) {
#pragma unroll
    for (int kb = 0; kb < 2; kb++)
#pragma unroll
        for (int nb = 0; nb < 4; nb++) {
            uint2 b = sB[(kb * 4 + nb) * 32 + lane];
            mma16(C[nb][0], C[nb][1], C[nb][2], C[nb][3],
                  A[kb][0], A[kb][1], A[kb][2], A[kb][3], b.x, b.y);
        }
}

__device__ __forceinline__ void c2a(const float C[4][4], unsigned A[2][4]) {
#pragma unroll
    for (int kb = 0; kb < 2; kb++) {
        A[kb][0] = packh2(C[2 * kb][0],     C[2 * kb][1]);
        A[kb][1] = packh2(C[2 * kb][2],     C[2 * kb][3]);
        A[kb][2] = packh2(C[2 * kb + 1][0], C[2 * kb + 1][1]);
        A[kb][3] = packh2(C[2 * kb + 1][2], C[2 * kb + 1][3]);
    }
}
__device__ __forceinline__ void lrelu16(float C[4][4]) {
#pragma unroll
    for (int b = 0; b < 4; b++)
#pragma unroll
        for (int r = 0; r < 4; r++) C[b][r] = lrelu(C[b][r]);
}

__device__ __forceinline__ void gather_p(const uint2* __restrict__ r0,
                                         const uint2* __restrict__ r1,
                                         unsigned A[2][4], int t) {
#pragma unroll
    for (int kb = 0; kb < 2; kb++) {
        uint2 v0 = r0[kb * 4 + t];
        uint2 v1 = r1[kb * 4 + t];
        A[kb][0] = v0.x; A[kb][2] = v0.y;
        A[kb][1] = v1.x; A[kb][3] = v1.y;
    }
}

__device__ __forceinline__ void scath(unsigned* rowA, unsigned* rowB,
                                      const float C[4][4], int t) {
#pragma unroll
    for (int kb = 0; kb < 2; kb++) {
        unsigned a0 = packh2(C[2 * kb][0],     C[2 * kb][1]);
        unsigned a1 = packh2(C[2 * kb + 1][0], C[2 * kb + 1][1]);
        red_h2v2(rowA + kb * 8 + 2 * t, a0, a1);
        unsigned b0 = packh2(C[2 * kb][2],     C[2 * kb][3]);
        unsigned b1 = packh2(C[2 * kb + 1][2], C[2 * kb + 1][3]);
        red_h2v2(rowB + kb * 8 + 2 * t, b0, b1);
    }
}

__device__ __forceinline__ void binit_s(float C[4][4], const float* sB, int t) {
#pragma unroll
    for (int nb = 0; nb < 4; nb++) {
        float2 B2 = *(const float2*)&sB[8 * nb + 2 * t];
        C[nb][0] = B2.x; C[nb][1] = B2.y; C[nb][2] = B2.x; C[nb][3] = B2.y;
    }
}
__device__ __forceinline__ void pqinit_s(float C[4][4], const float* sP, const float* sQ,
                                         float aA, float aB, int t) {
#pragma unroll
    for (int nb = 0; nb < 4; nb++) {
        float2 P = *(const float2*)&sP[8 * nb + 2 * t];
        float2 Q = *(const float2*)&sQ[8 * nb + 2 * t];
        C[nb][0] = fmaf(aA, P.x, Q.x); C[nb][1] = fmaf(aA, P.y, Q.y);
        C[nb][2] = fmaf(aB, P.x, Q.x); C[nb][3] = fmaf(aB, P.y, Q.y);
    }
}
__device__ __forceinline__ void ldw8(uint2 W[8], const uint2* s, int lane) {
#pragma unroll
    for (int p = 0; p < 8; p++) W[p] = s[p * 32 + lane];
}
__device__ __forceinline__ void cpA(unsigned D_[2][4], const unsigned S[2][4]) {
#pragma unroll
    for (int kb = 0; kb < 2; kb++)
#pragma unroll
        for (int r = 0; r < 4; r++) D_[kb][r] = S[kb][r];
}

__device__ void fill_bfrag(uint2* dst, const float* __restrict__ W, int kblocks) {
    for (int i = threadIdx.x; i < kblocks * 4 * 32; i += blockDim.x) {
        int lane = i & 31, pi = i >> 5;
        int kb = pi >> 2, nb = pi & 3;
        int t = lane & 3, g = lane >> 2;
        int col = 8 * nb + g;
        int k0r = 16 * kb + 2 * t;
        uint2 v;
        v.x = packh2(W[k0r * 32 + col],       W[(k0r + 1) * 32 + col]);
        v.y = packh2(W[(k0r + 8) * 32 + col], W[(k0r + 9) * 32 + col]);
        dst[pi * 32 + lane] = v;
    }
}

// compute F = W2 @ W1n (both row-major 32x32) into smem fp32
__device__ void matprod(float* sF, const float* __restrict__ W2,
                        const float* __restrict__ W1n) {
    for (int i = threadIdx.x; i < 1024; i += blockDim.x) {
        int r = i >> 5, c = i & 31;
        float s = 0.f;
#pragma unroll
        for (int k = 0; k < 32; k++) s = fmaf(W2[r * 32 + k], W1n[k * 32 + c], s);
        sF[i] = s;
    }
}

// ---------------- init / recip ----------------
__global__ void kinit() {
    int i = blockIdx.x * blockDim.x + threadIdx.x;
    if (i < N_NODES * 32) g_sh[i] = 0u;
    if (i < N_NODES)      g_dsum[i] = 0.f;
}
__global__ void kdiv() {
    int i = blockIdx.x * blockDim.x + threadIdx.x;
    if (i < N_NODES) g_dsum[i] = 1.0f / g_dsum[i];
}

// ---------------- K0: t0 = TMLP0(h0) (rank-1 folded) -> fp16 scatter s0 -----------
__global__ __launch_bounds__(128, 5)
void k0(const float* __restrict__ ea, const int* __restrict__ idx,
        const float* __restrict__ w_in, const float* __restrict__ b_in,
        const float* __restrict__ tw1, const float* __restrict__ tb1,
        const float* __restrict__ tw2, const float* __restrict__ tb2) {
    __shared__ uint2 sT2[256];
    __shared__ __align__(8) float sPT[32], sQT[32], sTB2[32];
    int tid = threadIdx.x;
    if (tid < 32) {
        float p = 0.f, qv = 0.f;
        for (int k = 0; k < 32; ++k) {
            p  = fmaf(w_in[k], tw1[k * 32 + tid], p);
            qv = fmaf(b_in[k], tw1[k * 32 + tid], qv);
        }
        sPT[tid] = p; sQT[tid] = qv + tb1[tid];
        sTB2[tid] = tb2[tid];
    }
    fill_bfrag(sT2, tw2, 2);
    __syncthreads();

    int lane = tid & 31, warp = tid >> 5;
    int t = lane & 3, g = lane >> 2;
    uint2 Wt2[8]; ldw8(Wt2, sT2, lane);

    for (int tile = blockIdx.x * 4 + warp; tile < NTILES; tile += gridDim.x * 4) {
        int e0 = tile * 16;
        int eA = e0 + g, eB = eA + 8;
        float aA = ea[eA], aB = ea[eB];
        int nA = idx[eA], nB = idx[eB];

        unsigned A[2][4];
#pragma unroll
        for (int kb = 0; kb < 2; kb++) {
            int c0 = 16 * kb + 2 * t;
            float2 P0 = *(const float2*)&sPT[c0],     Q0 = *(const float2*)&sQT[c0];
            float2 P1 = *(const float2*)&sPT[c0 + 8], Q1 = *(const float2*)&sQT[c0 + 8];
            A[kb][0] = packh2(lrelu(fmaf(aA, P0.x, Q0.x)), lrelu(fmaf(aA, P0.y, Q0.y)));
            A[kb][1] = packh2(lrelu(fmaf(aB, P0.x, Q0.x)), lrelu(fmaf(aB, P0.y, Q0.y)));
            A[kb][2] = packh2(lrelu(fmaf(aA, P1.x, Q1.x)), lrelu(fmaf(aA, P1.y, Q1.y)));
            A[kb][3] = packh2(lrelu(fmaf(aB, P1.x, Q1.x)), lrelu(fmaf(aB, P1.y, Q1.y)));
        }
        float C[4][4];
        binit_s(C, sTB2, t);
        mm_tile_r(A, Wt2, C);
        scath(g_sh + (size_t)nA * 32, g_sh + (size_t)nB * 32, C, t);
    }
}

// ---- K1 (FUSED): z = lrelu(PQ + s0@U1b); t = lrelu(z@(U2*T1)+bF)@T2+TB2 -> s1 ----
__global__ __launch_bounds__(128, 4)
void k1(const float* __restrict__ ea, const int* __restrict__ idx,
        const float* __restrict__ w_in, const float* __restrict__ b_in,
        const float* __restrict__ tw1, const float* __restrict__ tb1,
        const float* __restrict__ tw2, const float* __restrict__ tb2,
        const float* __restrict__ uw1, const float* __restrict__ ub1,
        const float* __restrict__ uw2, const float* __restrict__ ub2) {
    __shared__ uint2 sU1b[256], sF[256], sT2[256];
    __shared__ float sScr[1024];
    __shared__ __align__(8) float sPU[32], sQU[32], sBF[32], sTB2[32];
    int tid = threadIdx.x;
    if (tid < 32) {
        float p = 0.f, qv = 0.f, bf = 0.f;
        for (int k = 0; k < 32; ++k) {
            p  = fmaf(w_in[k], uw1[k * 32 + tid], p);
            qv = fmaf(b_in[k], uw1[k * 32 + tid], qv);
            bf = fmaf(ub2[k], tw1[1024 + k * 32 + tid], bf);   // UB2 @ T1
        }
        sPU[tid] = p; sQU[tid] = qv + ub1[tid];
        sBF[tid] = bf + tb1[32 + tid];
        sTB2[tid] = tb2[32 + tid];
    }
    fill_bfrag(sU1b, uw1 + 1024, 2);   // uw1[0] rows 32..63
    fill_bfrag(sT2,  tw2 + 1024, 2);   // tw2[1]
    matprod(sScr, uw2, tw1 + 1024);    // F = U2 @ T1
    __syncthreads();
    fill_bfrag(sF, sScr, 2);
    __syncthreads();

    int lane = tid & 31, warp = tid >> 5;
    int t = lane & 3, g = lane >> 2;
    uint2 Wu1b[8], WF[8], Wt2[8];
    ldw8(Wu1b, sU1b, lane); ldw8(WF, sF, lane); ldw8(Wt2, sT2, lane);

    const int stride = gridDim.x * 4;
    int tile = blockIdx.x * 4 + warp;
    if (tile >= NTILES) return;

    float aA = ea[tile * 16 + g], aB = ea[tile * 16 + g + 8];
    int nA = idx[tile * 16 + g], nB = idx[tile * 16 + g + 8];
    unsigned A[2][4];
    gather_p((const uint2*)g_sh + (size_t)nA * 16,
             (const uint2*)g_sh + (size_t)nB * 16, A, t);

    while (true) {
        int tn = tile + stride;
        bool has = tn < NTILES;
        int tc = has ? tn : tile;
        float aAn = ea[tc * 16 + g], aBn = ea[tc * 16 + g + 8];
        int nAn = idx[tc * 16 + g], nBn = idx[tc * 16 + g + 8];
        unsigned An[2][4];
        gather_p((const uint2*)g_sh + (size_t)nAn * 16,
                 (const uint2*)g_sh + (size_t)nBn * 16, An, t);

        float C[4][4];
        pqinit_s(C, sPU, sQU, aA, aB, t);
        mm_tile_r(A, Wu1b, C);
        lrelu16(C);
        c2a(C, A);

        binit_s(C, sBF, t);
        mm_tile_r(A, WF, C);           // fused U2*T1
        lrelu16(C);
        c2a(C, A);

        binit_s(C, sTB2, t);
        mm_tile_r(A, Wt2, C);
        scath(g_sh + (size_t)nA * 32 + 16, g_sh + (size_t)nB * 32 + 16, C, t);

        if (!has) break;
        tile = tn;
        aA = aAn; aB = aBn; nA = nAn; nB = nBn;
        cpA(A, An);
    }
}

// ---- K2 (FUSED): z->D (via U20*U1h fused)->v1 (via U2*H1b fused)->v2->exp --------
__global__ __launch_bounds__(128, 4)
void k2(const float* __restrict__ ea, const int* __restrict__ idx,
        const float* __restrict__ w_in, const float* __restrict__ b_in,
        const float* __restrict__ uw1, const float* __restrict__ ub1,
        const float* __restrict__ uw2, const float* __restrict__ ub2,
        const float* __restrict__ hw1, const float* __restrict__ hb1,
        const float* __restrict__ hw2, const float* __restrict__ hb2,
        const float* __restrict__ hw3, const float* __restrict__ hb3,
        float* __restrict__ out) {
    __shared__ uint2 sU1b0[256], sF1[256], sU1s[256], sF2[256], sH2[256];
    __shared__ float sScr[1024];
    __shared__ __align__(8) float sPU[32], sQU[32], sBD[32], sPH[32], sQHp[32],
                                  sHB2[32], sH3[32];
    __shared__ float sHB3;
    int tid = threadIdx.x;
    const float* u1 = uw1 + 2048;               // uw1[1] (64x32)
    if (tid < 32) {
        float p = 0.f, qv = 0.f, pu = 0.f, qu = 0.f, bd = 0.f, bh = 0.f;
        for (int k = 0; k < 32; ++k) {
            p  = fmaf(w_in[k], hw1[k * 32 + tid], p);
            qv = fmaf(b_in[k], hw1[k * 32 + tid], qv);
            pu = fmaf(w_in[k], uw1[k * 32 + tid], pu);
            qu = fmaf(b_in[k], uw1[k * 32 + tid], qu);
            bd = fmaf(ub2[k],      u1[k * 32 + tid], bd);          // UB20 @ U1h
            bh = fmaf(ub2[32 + k], hw1[1024 + k * 32 + tid], bh);  // UB2(l1) @ H1b
        }
        sPH[tid] = p;  sQHp[tid] = qv + hb1[tid] + bh;
        sPU[tid] = pu; sQU[tid]  = qu + ub1[tid];
        sBD[tid] = bd + ub1[32 + tid];
        sHB2[tid] = hb2[tid];
        sH3[tid]  = hw3[tid];
    }
    if (tid == 0) sHB3 = hb3[0];
    fill_bfrag(sU1b0, uw1 + 1024, 2);   // uw1[0] rows 32..63
    fill_bfrag(sU1s,  u1 + 1024, 2);    // uw1[1] rows 32..63 (s-part)
    fill_bfrag(sH2,   hw2, 2);
    matprod(sScr, uw2, u1);             // F1 = U20 @ U1h
    __syncthreads();
    fill_bfrag(sF1, sScr, 2);
    __syncthreads();
    matprod(sScr, uw2 + 1024, hw1 + 1024);  // F2 = U2(l1) @ H1b
    __syncthreads();
    fill_bfrag(sF2, sScr, 2);
    __syncthreads();

    int lane = tid & 31, warp = tid >> 5;
    int t = lane & 3, g = lane >> 2;
    uint2 WF1[8], Wu1s[8];
    ldw8(WF1, sF1, lane); ldw8(Wu1s, sU1s, lane);
    float hb3v = sHB3;

    const int stride = gridDim.x * 4;
    int tile = blockIdx.x * 4 + warp;
    if (tile >= NTILES) return;

    float aA = ea[tile * 16 + g], aB = ea[tile * 16 + g + 8];
    int nA = idx[tile * 16 + g], nB = idx[tile * 16 + g + 8];
    unsigned A0[2][4], A1[2][4];
    gather_p((const uint2*)g_sh + (size_t)nA * 16,
             (const uint2*)g_sh + (size_t)nB * 16, A0, t);
    gather_p((const uint2*)g_sh + (size_t)nA * 16 + 8,
             (const uint2*)g_sh + (size_t)nB * 16 + 8, A1, t);

    while (true) {
        int tn = tile + stride;
        bool has = tn < NTILES;
        int tc = has ? tn : tile;
        float aAn = ea[tc * 16 + g], aBn = ea[tc * 16 + g + 8];
        int nAn = idx[tc * 16 + g], nBn = idx[tc * 16 + g + 8];
        unsigned A0n[2][4], A1n[2][4];
        gather_p((const uint2*)g_sh + (size_t)nAn * 16,
                 (const uint2*)g_sh + (size_t)nBn * 16, A0n, t);
        gather_p((const uint2*)g_sh + (size_t)nAn * 16 + 8,
                 (const uint2*)g_sh + (size_t)nBn * 16 + 8, A1n, t);

        // z = lrelu(PQ_U + s0@U1b0)
        float C[4][4];
        pqinit_s(C, sPU, sQU, aA, aB, t);
        mm_tile_s(A0, sU1b0, C, lane);
        lrelu16(C);
        unsigned A[2][4];
        c2a(C, A);

        // D = lrelu(BD + z@F1 + s1@U1s)
        binit_s(C, sBD, t);
        mm_tile_r(A, WF1, C);
        mm_tile_r(A1, Wu1s, C);
        lrelu16(C);
        c2a(C, A);

        // v1 = lrelu(a*PH + QH' + D@F2)
        pqinit_s(C, sPH, sQHp, aA, aB, t);
        mm_tile_s(A, sF2, C, lane);
        lrelu16(C);
        c2a(C, A);

        // v2 = lrelu(v1@H2 + HB2)
        binit_s(C, sHB2, t);
        mm_tile_s(A, sH2, C, lane);
        lrelu16(C);

        float dA = 0.f, dB = 0.f;
#pragma unroll
        for (int nb = 0; nb < 4; nb++) {
            float2 h3 = *(const float2*)&sH3[8 * nb + 2 * t];
            dA = fmaf(C[nb][0], h3.x, dA); dA = fmaf(C[nb][1], h3.y, dA);
            dB = fmaf(C[nb][2], h3.x, dB); dB = fmaf(C[nb][3], h3.y, dB);
        }
        dA += __shfl_xor_sync(0xffffffffu, dA, 1);
        dA += __shfl_xor_sync(0xffffffffu, dA, 2);
        dB += __shfl_xor_sync(0xffffffffu, dB, 1);
        dB += __shfl_xor_sync(0xffffffffu, dB, 2);

        if (t == 0) {
            float exA = __expf(dA + hb3v), exB = __expf(dB + hb3v);
            out[tile * 16 + g] = exA;
            out[tile * 16 + g + 8] = exB;
            red_add1(&g_dsum[nA], exA);
            red_add1(&g_dsum[nB], exB);
        }

        if (!has) break;
        tile = tn;
        aA = aAn; aB = aBn; nA = nAn; nB = nBn;
        cpA(A0, A0n); cpA(A1, A1n);
    }
}

// ---------------- K4: normalize (multiply by precomputed reciprocal) --------------
__global__ void k4(const int* __restrict__ idx, float* __restrict__ out) {
    int e = blockIdx.x * blockDim.x + threadIdx.x;
    if (e >= E_EDGES) return;
    out[e] = out[e] * g_dsum[idx[e]];
}

// ---------------- launcher ----------------
extern "C" void kernel_launch(void* const* d_in, const int* in_sizes, int n_in,
                              void* d_out, int out_size) {
    const float* ea   = (const float*)d_in[0];
    const int*   eidx = (const int*)d_in[1];
    const float* w_in = (const float*)d_in[2];
    const float* b_in = (const float*)d_in[3];
    const float* tw1  = (const float*)d_in[4];
    const float* tb1  = (const float*)d_in[5];
    const float* tw2  = (const float*)d_in[6];
    const float* tb2  = (const float*)d_in[7];
    const float* uw1  = (const float*)d_in[8];
    const float* ub1  = (const float*)d_in[9];
    const float* uw2  = (const float*)d_in[10];
    const float* ub2  = (const float*)d_in[11];
    const float* hw1  = (const float*)d_in[12];
    const float* hb1  = (const float*)d_in[13];
    const float* hw2  = (const float*)d_in[14];
    const float* hb2  = (const float*)d_in[15];
    const float* hw3  = (const float*)d_in[16];
    const float* hb3  = (const float*)d_in[17];
    float* out = (float*)d_out;

    const int TB = 256;
    kinit<<<(N_NODES * 32 + TB - 1) / TB, TB>>>();
    const int GB = 2048;
    k0<<<GB, 128>>>(ea, eidx, w_in, b_in, tw1, tb1, tw2, tb2);
    k1<<<GB, 128>>>(ea, eidx, w_in, b_in, tw1, tb1, tw2, tb2, uw1, ub1, uw2, ub2);
    k2<<<GB, 128>>>(ea, eidx, w_in, b_in, uw1, ub1, uw2, ub2,
                    hw1, hb1, hw2, hb2, hw3, hb3, out);
    kdiv<<<(N_NODES + TB - 1) / TB, TB>>>();
    int gb = (E_EDGES + TB - 1) / TB;
    k4<<<gb, TB>>>(eidx, out);
}

// round 15
// speedup vs baseline: 1.1494x; 1.1494x over previous
#include <cuda_runtime.h>

#define E_EDGES 2000000
#define N_NODES 50000
#define D 32
#define NTILES (E_EDGES / 16)

// ---------------- scratch ----------------
// fp16 node table, VECTOR-PERMUTED: per node 8 uint4 slots.
// slots 0..3  = s0 (lane t owns slot t:   words {nb0,nb1,nb2,nb3} of its columns)
// slots 4..7  = s1 (lane t owns slot 4+t)
__device__ __align__(16) uint4 g_s4[N_NODES * 8];
__device__ float g_dsum[N_NODES];         // softmax denominators (-> reciprocals)

__device__ __forceinline__ float lrelu(float x) { return fmaxf(x, 0.01f * x); }
__device__ __forceinline__ void red_add1(float* p, float v) {
    asm volatile("red.global.add.f32 [%0], %1;" :: "l"(p), "f"(v) : "memory");
}
__device__ __forceinline__ unsigned packh2(float lo, float hi) {
    unsigned r; asm("cvt.rn.f16x2.f32 %0, %1, %2;" : "=r"(r) : "f"(hi), "f"(lo)); return r;
}

__device__ __forceinline__ void mma16(float& c0, float& c1, float& c2, float& c3,
                                      unsigned a0, unsigned a1, unsigned a2, unsigned a3,
                                      unsigned b0, unsigned b1) {
    asm("mma.sync.aligned.m16n8k16.row.col.f32.f16.f16.f32 "
        "{%0,%1,%2,%3},{%4,%5,%6,%7},{%8,%9},{%0,%1,%2,%3};"
        : "+f"(c0), "+f"(c1), "+f"(c2), "+f"(c3)
        : "r"(a0), "r"(a1), "r"(a2), "r"(a3), "r"(b0), "r"(b1));
}

__device__ __forceinline__ void mm_tile_r(const unsigned A[2][4], const uint2 W[8],
                                          float C[4][4]) {
#pragma unroll
    for (int kb = 0; kb < 2; kb++)
#pragma unroll
        for (int nb = 0; nb < 4; nb++) {
            uint2 b = W[kb * 4 + nb];
            mma16(C[nb][0], C[nb][1], C[nb][2], C[nb][3],
                  A[kb][0], A[kb][1], A[kb][2], A[kb][3], b.x, b.y);
        }
}
__device__ __forceinline__ void mm_tile_s(const unsigned A[2][4], const uint2* sB,
                                          float C[4][4], int lane) {
#pragma unroll
    for (int kb = 0; kb < 2; kb++)
#pragma unroll
        for (int nb = 0; nb < 4; nb++) {
            uint2 b = sB[(kb * 4 + nb) * 32 + lane];
            mma16(C[nb][0], C[nb][1], C[nb][2], C[nb][3],
                  A[kb][0], A[kb][1], A[kb][2], A[kb][3], b.x, b.y);
        }
}

__device__ __forceinline__ void c2a(const float C[4][4], unsigned A[2][4]) {
#pragma unroll
    for (int kb = 0; kb < 2; kb++) {
        A[kb][0] = packh2(C[2 * kb][0],     C[2 * kb][1]);
        A[kb][1] = packh2(C[2 * kb][2],     C[2 * kb][3]);
        A[kb][2] = packh2(C[2 * kb + 1][0], C[2 * kb + 1][1]);
        A[kb][3] = packh2(C[2 * kb + 1][2], C[2 * kb + 1][3]);
    }
}
__device__ __forceinline__ void lrelu16(float C[4][4]) {
#pragma unroll
    for (int b = 0; b < 4; b++)
#pragma unroll
        for (int r = 0; r < 4; r++) C[b][r] = lrelu(C[b][r]);
}

// vector gather: one LDG.128 per node row (pointers already offset to lane slot)
__device__ __forceinline__ void gather_v(const uint4* __restrict__ r0,
                                         const uint4* __restrict__ r1,
                                         unsigned A[2][4]) {
    uint4 v0 = *r0, v1 = *r1;
    A[0][0] = v0.x; A[0][2] = v0.y; A[1][0] = v0.z; A[1][2] = v0.w;
    A[0][1] = v1.x; A[0][3] = v1.y; A[1][1] = v1.z; A[1][3] = v1.w;
}

// vector scatter: one red.v4.f16x2 (16B) per node row
__device__ __forceinline__ void scath_v(uint4* pA, uint4* pB, const float C[4][4]) {
    unsigned w0 = packh2(C[0][0], C[0][1]), w1 = packh2(C[1][0], C[1][1]);
    unsigned w2 = packh2(C[2][0], C[2][1]), w3 = packh2(C[3][0], C[3][1]);
    asm volatile("red.global.add.noftz.v4.f16x2 [%0], {%1,%2,%3,%4};"
                 :: "l"(pA), "r"(w0), "r"(w1), "r"(w2), "r"(w3) : "memory");
    unsigned x0 = packh2(C[0][2], C[0][3]), x1 = packh2(C[1][2], C[1][3]);
    unsigned x2 = packh2(C[2][2], C[2][3]), x3 = packh2(C[3][2], C[3][3]);
    asm volatile("red.global.add.noftz.v4.f16x2 [%0], {%1,%2,%3,%4};"
                 :: "l"(pB), "r"(x0), "r"(x1), "r"(x2), "r"(x3) : "memory");
}

__device__ __forceinline__ void binit_s(float C[4][4], const float* sB, int t) {
#pragma unroll
    for (int nb = 0; nb < 4; nb++) {
        float2 B2 = *(const float2*)&sB[8 * nb + 2 * t];
        C[nb][0] = B2.x; C[nb][1] = B2.y; C[nb][2] = B2.x; C[nb][3] = B2.y;
    }
}
__device__ __forceinline__ void pqinit_s(float C[4][4], const float* sP, const float* sQ,
                                         float aA, float aB, int t) {
#pragma unroll
    for (int nb = 0; nb < 4; nb++) {
        float2 P = *(const float2*)&sP[8 * nb + 2 * t];
        float2 Q = *(const float2*)&sQ[8 * nb + 2 * t];
        C[nb][0] = fmaf(aA, P.x, Q.x); C[nb][1] = fmaf(aA, P.y, Q.y);
        C[nb][2] = fmaf(aB, P.x, Q.x); C[nb][3] = fmaf(aB, P.y, Q.y);
    }
}
__device__ __forceinline__ void ldw8(uint2 W[8], const uint2* s, int lane) {
#pragma unroll
    for (int p = 0; p < 8; p++) W[p] = s[p * 32 + lane];
}
__device__ __forceinline__ void cpA(unsigned D_[2][4], const unsigned S[2][4]) {
#pragma unroll
    for (int kb = 0; kb < 2; kb++)
#pragma unroll
        for (int r = 0; r < 4; r++) D_[kb][r] = S[kb][r];
}

__device__ void fill_bfrag(uint2* dst, const float* __restrict__ W, int kblocks) {
    for (int i = threadIdx.x; i < kblocks * 4 * 32; i += blockDim.x) {
        int lane = i & 31, pi = i >> 5;
        int kb = pi >> 2, nb = pi & 3;
        int t = lane & 3, g = lane >> 2;
        int col = 8 * nb + g;
        int k0r = 16 * kb + 2 * t;
        uint2 v;
        v.x = packh2(W[k0r * 32 + col],       W[(k0r + 1) * 32 + col]);
        v.y = packh2(W[(k0r + 8) * 32 + col], W[(k0r + 9) * 32 + col]);
        dst[pi * 32 + lane] = v;
    }
}

// F = W2 @ W1n into smem fp32
__device__ void matprod(float* sF, const float* __restrict__ W2,
                        const float* __restrict__ W1n) {
    for (int i = threadIdx.x; i < 1024; i += blockDim.x) {
        int r = i >> 5, c = i & 31;
        float s = 0.f;
#pragma unroll
        for (int k = 0; k < 32; k++) s = fmaf(W2[r * 32 + k], W1n[k * 32 + c], s);
        sF[i] = s;
    }
}

// ---------------- init / recip ----------------
__global__ void kinit() {
    int i = blockIdx.x * blockDim.x + threadIdx.x;
    if (i < N_NODES * 8) g_s4[i] = make_uint4(0u, 0u, 0u, 0u);
    if (i < N_NODES)     g_dsum[i] = 0.f;
}
__global__ void kdiv() {
    int i = blockIdx.x * blockDim.x + threadIdx.x;
    if (i < N_NODES) g_dsum[i] = 1.0f / g_dsum[i];
}

// ---------------- K0: t0 = TMLP0(h0) (rank-1 folded) -> v4 scatter s0 -------------
__global__ __launch_bounds__(128, 5)
void k0(const float* __restrict__ ea, const int* __restrict__ idx,
        const float* __restrict__ w_in, const float* __restrict__ b_in,
        const float* __restrict__ tw1, const float* __restrict__ tb1,
        const float* __restrict__ tw2, const float* __restrict__ tb2) {
    __shared__ uint2 sT2[256];
    __shared__ __align__(8) float sPT[32], sQT[32], sTB2[32];
    int tid = threadIdx.x;
    if (tid < 32) {
        float p = 0.f, qv = 0.f;
        for (int k = 0; k < 32; ++k) {
            p  = fmaf(w_in[k], tw1[k * 32 + tid], p);
            qv = fmaf(b_in[k], tw1[k * 32 + tid], qv);
        }
        sPT[tid] = p; sQT[tid] = qv + tb1[tid];
        sTB2[tid] = tb2[tid];
    }
    fill_bfrag(sT2, tw2, 2);
    __syncthreads();

    int lane = tid & 31, warp = tid >> 5;
    int t = lane & 3, g = lane >> 2;
    uint2 Wt2[8]; ldw8(Wt2, sT2, lane);

    for (int tile = blockIdx.x * 4 + warp; tile < NTILES; tile += gridDim.x * 4) {
        int e0 = tile * 16;
        int eA = e0 + g, eB = eA + 8;
        float aA = ea[eA], aB = ea[eB];
        int nA = idx[eA], nB = idx[eB];

        unsigned A[2][4];
#pragma unroll
        for (int kb = 0; kb < 2; kb++) {
            int c0 = 16 * kb + 2 * t;
            float2 P0 = *(const float2*)&sPT[c0],     Q0 = *(const float2*)&sQT[c0];
            float2 P1 = *(const float2*)&sPT[c0 + 8], Q1 = *(const float2*)&sQT[c0 + 8];
            A[kb][0] = packh2(lrelu(fmaf(aA, P0.x, Q0.x)), lrelu(fmaf(aA, P0.y, Q0.y)));
            A[kb][1] = packh2(lrelu(fmaf(aB, P0.x, Q0.x)), lrelu(fmaf(aB, P0.y, Q0.y)));
            A[kb][2] = packh2(lrelu(fmaf(aA, P1.x, Q1.x)), lrelu(fmaf(aA, P1.y, Q1.y)));
            A[kb][3] = packh2(lrelu(fmaf(aB, P1.x, Q1.x)), lrelu(fmaf(aB, P1.y, Q1.y)));
        }
        float C[4][4];
        binit_s(C, sTB2, t);
        mm_tile_r(A, Wt2, C);
        scath_v(g_s4 + (size_t)nA * 8 + t, g_s4 + (size_t)nB * 8 + t, C);
    }
}

// ---- K1 (FUSED, all-register weights): z -> t1 via (U2*T1) -> v4 scatter s1 ------
__global__ __launch_bounds__(128, 4)
void k1(const float* __restrict__ ea, const int* __restrict__ idx,
        const float* __restrict__ w_in, const float* __restrict__ b_in,
        const float* __restrict__ tw1, const float* __restrict__ tb1,
        const float* __restrict__ tw2, const float* __restrict__ tb2,
        const float* __restrict__ uw1, const float* __restrict__ ub1,
        const float* __restrict__ uw2, const float* __restrict__ ub2) {
    __shared__ uint2 sU1b[256], sF[256], sT2[256];
    __shared__ float sScr[1024];
    __shared__ __align__(8) float sPU[32], sQU[32], sBF[32], sTB2[32];
    int tid = threadIdx.x;
    if (tid < 32) {
        float p = 0.f, qv = 0.f, bf = 0.f;
        for (int k = 0; k < 32; ++k) {
            p  = fmaf(w_in[k], uw1[k * 32 + tid], p);
            qv = fmaf(b_in[k], uw1[k * 32 + tid], qv);
            bf = fmaf(ub2[k], tw1[1024 + k * 32 + tid], bf);   // UB2 @ T1
        }
        sPU[tid] = p; sQU[tid] = qv + ub1[tid];
        sBF[tid] = bf + tb1[32 + tid];
        sTB2[tid] = tb2[32 + tid];
    }
    fill_bfrag(sU1b, uw1 + 1024, 2);
    fill_bfrag(sT2,  tw2 + 1024, 2);
    matprod(sScr, uw2, tw1 + 1024);    // F = U2 @ T1
    __syncthreads();
    fill_bfrag(sF, sScr, 2);
    __syncthreads();

    int lane = tid & 31, warp = tid >> 5;
    int t = lane & 3, g = lane >> 2;
    uint2 Wu1b[8], WF[8], Wt2[8];
    ldw8(Wu1b, sU1b, lane); ldw8(WF, sF, lane); ldw8(Wt2, sT2, lane);

    const int stride = gridDim.x * 4;
    int tile = blockIdx.x * 4 + warp;
    if (tile >= NTILES) return;

    float aA = ea[tile * 16 + g], aB = ea[tile * 16 + g + 8];
    int nA = idx[tile * 16 + g], nB = idx[tile * 16 + g + 8];
    unsigned A[2][4];
    gather_v(g_s4 + (size_t)nA * 8 + t, g_s4 + (size_t)nB * 8 + t, A);

    while (true) {
        int tn = tile + stride;
        bool has = tn < NTILES;
        int tc = has ? tn : tile;
        float aAn = ea[tc * 16 + g], aBn = ea[tc * 16 + g + 8];
        int nAn = idx[tc * 16 + g], nBn = idx[tc * 16 + g + 8];
        unsigned An[2][4];
        gather_v(g_s4 + (size_t)nAn * 8 + t, g_s4 + (size_t)nBn * 8 + t, An);

        float C[4][4];
        pqinit_s(C, sPU, sQU, aA, aB, t);
        mm_tile_r(A, Wu1b, C);
        lrelu16(C);
        c2a(C, A);

        binit_s(C, sBF, t);
        mm_tile_r(A, WF, C);           // fused U2*T1
        lrelu16(C);
        c2a(C, A);

        binit_s(C, sTB2, t);
        mm_tile_r(A, Wt2, C);
        scath_v(g_s4 + (size_t)nA * 8 + 4 + t, g_s4 + (size_t)nB * 8 + 4 + t, C);

        if (!has) break;
        tile = tn;
        aA = aAn; aB = aBn; nA = nAn; nB = nBn;
        cpA(A, An);
    }
}

// ---- K2 (UNFUSED, R13 structure): recompute h1; UPD1; head; exp; red denom -------
__global__ __launch_bounds__(128, 4)
void k2(const float* __restrict__ ea, const int* __restrict__ idx,
        const float* __restrict__ w_in, const float* __restrict__ b_in,
        const float* __restrict__ uw1, const float* __restrict__ ub1,
        const float* __restrict__ uw2, const float* __restrict__ ub2,
        const float* __restrict__ hw1, const float* __restrict__ hb1,
        const float* __restrict__ hw2, const float* __restrict__ hb2,
        const float* __restrict__ hw3, const float* __restrict__ hb3,
        float* __restrict__ out) {
    __shared__ uint2 sU1[512];                  // uw1[1]: kb0..1 h-part, kb2..3 s-part
    __shared__ uint2 sU2[256], sH1b[256], sH2[256];
    __shared__ uint2 sU1b0[256], sU20[256];     // layer-0 weights for h1 recompute
    __shared__ __align__(8) float sUB1[32], sUB2[32], sPH[32], sQH[32], sHB2[32], sH3[32];
    __shared__ __align__(8) float sPU[32], sQU[32], sUB20[32];
    __shared__ float sHB3;
    int tid = threadIdx.x;
    const float* u1 = uw1 + 2048;
    if (tid < 32) {
        float p = 0.f, qv = 0.f, pu = 0.f, qu = 0.f;
        for (int k = 0; k < 32; ++k) {
            p  = fmaf(w_in[k], hw1[k * 32 + tid], p);
            qv = fmaf(b_in[k], hw1[k * 32 + tid], qv);
            pu = fmaf(w_in[k], uw1[k * 32 + tid], pu);
            qu = fmaf(b_in[k], uw1[k * 32 + tid], qu);
        }
        sPH[tid] = p;  sQH[tid] = qv + hb1[tid];
        sPU[tid] = pu; sQU[tid] = qu + ub1[tid];
        sUB20[tid] = ub2[tid];
        sUB1[tid] = ub1[32 + tid];
        sUB2[tid] = ub2[32 + tid];
        sHB2[tid] = hb2[tid];
        sH3[tid]  = hw3[tid];
    }
    if (tid == 0) sHB3 = hb3[0];
    fill_bfrag(sU1,   u1, 4);
    fill_bfrag(sU2,   uw2 + 1024, 2);
    fill_bfrag(sH1b,  hw1 + 1024, 2);
    fill_bfrag(sH2,   hw2, 2);
    fill_bfrag(sU1b0, uw1 + 1024, 2);
    fill_bfrag(sU20,  uw2, 2);
    __syncthreads();

    int lane = tid & 31, warp = tid >> 5;
    int t = lane & 3, g = lane >> 2;
    uint2 Wu1h[8], Wu1s[8];
    ldw8(Wu1h, sU1, lane); ldw8(Wu1s, sU1 + 8 * 32, lane);
    float hb3v = sHB3;

    const int stride = gridDim.x * 4;
    int tile = blockIdx.x * 4 + warp;
    if (tile >= NTILES) return;

    float aA = ea[tile * 16 + g], aB = ea[tile * 16 + g + 8];
    int nA = idx[tile * 16 + g], nB = idx[tile * 16 + g + 8];
    unsigned A0[2][4], A1[2][4];
    gather_v(g_s4 + (size_t)nA * 8 + t,     g_s4 + (size_t)nB * 8 + t,     A0);
    gather_v(g_s4 + (size_t)nA * 8 + 4 + t, g_s4 + (size_t)nB * 8 + 4 + t, A1);

    while (true) {
        int tn = tile + stride;
        bool has = tn < NTILES;
        int tc = has ? tn : tile;
        float aAn = ea[tc * 16 + g], aBn = ea[tc * 16 + g + 8];
        int nAn = idx[tc * 16 + g], nBn = idx[tc * 16 + g + 8];
        unsigned A0n[2][4], A1n[2][4];
        gather_v(g_s4 + (size_t)nAn * 8 + t,     g_s4 + (size_t)nBn * 8 + t,     A0n);
        gather_v(g_s4 + (size_t)nAn * 8 + 4 + t, g_s4 + (size_t)nBn * 8 + 4 + t, A1n);

        // ---- recompute h1 from s0 frag ----
        float C[4][4];
        pqinit_s(C, sPU, sQU, aA, aB, t);
        mm_tile_s(A0, sU1b0, C, lane);
        lrelu16(C);
        unsigned A[2][4];
        c2a(C, A);
        float H[4][4];
        binit_s(H, sUB20, t);
        mm_tile_s(A, sU20, H, lane);    // H = h1
        c2a(H, A);

        // ---- layer-1 update ----
        binit_s(C, sUB1, t);
        mm_tile_r(A, Wu1h, C);
        mm_tile_r(A1, Wu1s, C);
        lrelu16(C);
        c2a(C, A);

        binit_s(H, sUB2, t);
        mm_tile_s(A, sU2, H, lane);     // H = h2
        c2a(H, A);

        // ---- head ----
        pqinit_s(C, sPH, sQH, aA, aB, t);
        mm_tile_s(A, sH1b, C, lane);
        lrelu16(C);
        c2a(C, A);
        binit_s(C, sHB2, t);
        mm_tile_s(A, sH2, C, lane);
        lrelu16(C);

        float dA = 0.f, dB = 0.f;
#pragma unroll
        for (int nb = 0; nb < 4; nb++) {
            float2 h3 = *(const float2*)&sH3[8 * nb + 2 * t];
            dA = fmaf(C[nb][0], h3.x, dA); dA = fmaf(C[nb][1], h3.y, dA);
            dB = fmaf(C[nb][2], h3.x, dB); dB = fmaf(C[nb][3], h3.y, dB);
        }
        dA += __shfl_xor_sync(0xffffffffu, dA, 1);
        dA += __shfl_xor_sync(0xffffffffu, dA, 2);
        dB += __shfl_xor_sync(0xffffffffu, dB, 1);
        dB += __shfl_xor_sync(0xffffffffu, dB, 2);

        if (t == 0) {
            float exA = __expf(dA + hb3v), exB = __expf(dB + hb3v);
            out[tile * 16 + g] = exA;
            out[tile * 16 + g + 8] = exB;
            red_add1(&g_dsum[nA], exA);
            red_add1(&g_dsum[nB], exB);
        }

        if (!has) break;
        tile = tn;
        aA = aAn; aB = aBn; nA = nAn; nB = nBn;
        cpA(A0, A0n); cpA(A1, A1n);
    }
}

// ---------------- K4: normalize (multiply by precomputed reciprocal) --------------
__global__ void k4(const int* __restrict__ idx, float* __restrict__ out) {
    int e = blockIdx.x * blockDim.x + threadIdx.x;
    if (e >= E_EDGES) return;
    out[e] = out[e] * g_dsum[idx[e]];
}

// ---------------- launcher ----------------
extern "C" void kernel_launch(void* const* d_in, const int* in_sizes, int n_in,
                              void* d_out, int out_size) {
    const float* ea   = (const float*)d_in[0];
    const int*   eidx = (const int*)d_in[1];
    const float* w_in = (const float*)d_in[2];
    const float* b_in = (const float*)d_in[3];
    const float* tw1  = (const float*)d_in[4];
    const float* tb1  = (const float*)d_in[5];
    const float* tw2  = (const float*)d_in[6];
    const float* tb2  = (const float*)d_in[7];
    const float* uw1  = (const float*)d_in[8];
    const float* ub1  = (const float*)d_in[9];
    const float* uw2  = (const float*)d_in[10];
    const float* ub2  = (const float*)d_in[11];
    const float* hw1  = (const float*)d_in[12];
    const float* hb1  = (const float*)d_in[13];
    const float* hw2  = (const float*)d_in[14];
    const float* hb2  = (const float*)d_in[15];
    const float* hw3  = (const float*)d_in[16];
    const float* hb3  = (const float*)d_in[17];
    float* out = (float*)d_out;

    const int TB = 256;
    kinit<<<(N_NODES * 8 + TB - 1) / TB, TB>>>();
    const int GB = 2048;
    k0<<<GB, 128>>>(ea, eidx, w_in, b_in, tw1, tb1, tw2, tb2);
    k1<<<GB, 128>>>(ea, eidx, w_in, b_in, tw1, tb1, tw2, tb2, uw1, ub1, uw2, ub2);
    k2<<<GB, 128>>>(ea, eidx, w_in, b_in, uw1, ub1, uw2, ub2,
                    hw1, hb1, hw2, hb2, hw3, hb3, out);
    kdiv<<<(N_NODES + TB - 1) / TB, TB>>>();
    int gb = (E_EDGES + TB - 1) / TB;
    k4<<<gb, TB>>>(eidx, out);
}